// round 14
// baseline (speedup 1.0000x reference)
#include <cuda_runtime.h>
#include <math.h>

#define NT 512
#define ROWS 8
#define LDH 132            // fp32 H row stride (132%32==4)

// ---- smem regions (u32 units) ----
#define OFF_H    0         // H fp32: 64 x 132            = 8448
#define OFF_SP1  8448      // hn split 64x144 / splitH 8x1168 = 9344
#define OFF_FK   17792     // K fp32 64x132; FFN: mid split (32x528 spans FK+FV)
#define OFF_FV   26240     // V fp32 64x132
#define OFF_QA   34688     // Q fp32 64x132 / att split 64x144 / hn2 split 32x144
#define OFF_SP2  43904     // x split 8x272 / attO split 64x144 / agg split 8x144
#define SMEM_U32 53120     // 212,480 bytes

// ---- packed (pre-split bf16) weight scratch: uint4{bh0,bh1,bl0,bl1} per [k16][jt][lane] ----
#define PK_WP     0
#define PK_L0     65536
#define PK_LSTR   57344
#define PK_WQ     0
#define PK_WK     4096
#define PK_WV     8192
#define PK_WO     12288
#define PK_WU     16384
#define PK_WF1    24576
#define PK_WF2    40960
#define PK_WA     237568
#define PK_WOUT   270336
#define PK_TOTAL  274432

__device__ uint4 g_packed[PK_TOTAL];

enum { EPI_STORE=0, EPI_GELU=2, EPI_ADD=3, EPI_RELU_ADD=4 };

__device__ __forceinline__ float gelu_f(float v) {
    return 0.5f * v * (1.0f + erff(v * 0.70710678118654752440f));
}

// ---- bf16 mma helpers ----
__device__ __forceinline__ void mma_bf16(float* d, const unsigned* a, const unsigned* b) {
    asm("mma.sync.aligned.m16n8k16.row.col.f32.bf16.bf16.f32 "
        "{%0,%1,%2,%3}, {%4,%5,%6,%7}, {%8,%9}, {%0,%1,%2,%3};"
        : "+f"(d[0]), "+f"(d[1]), "+f"(d[2]), "+f"(d[3])
        : "r"(a[0]), "r"(a[1]), "r"(a[2]), "r"(a[3]), "r"(b[0]), "r"(b[1]));
}
__device__ __forceinline__ unsigned cvt_bf16x2(float hi_elem, float lo_elem) {
    unsigned r;
    asm("cvt.rn.bf16x2.f32 %0, %1, %2;" : "=r"(r) : "f"(hi_elem), "f"(lo_elem));
    return r;
}
__device__ __forceinline__ float bf_lo(unsigned r) { return __uint_as_float(r << 16); }
__device__ __forceinline__ float bf_hi(unsigned r) { return __uint_as_float(r & 0xFFFF0000u); }
__device__ __forceinline__ void split_bf16(float x, float y, unsigned& hi, unsigned& lo) {
    hi = cvt_bf16x2(y, x);
    lo = cvt_bf16x2(y - bf_hi(hi), x - bf_lo(hi));
}
__device__ __forceinline__ int pslot(int p) { return (p < 4) ? p * 4 : (p - 4) * 4 + 2; }
__device__ __forceinline__ void store_split_pair(unsigned* row, int w, int p, float x, float y) {
    unsigned hi, lo; split_bf16(x, y, hi, lo);
    *(uint2*)(row + w * 16 + pslot(p)) = make_uint2(hi, lo);
}

// ---- weight pre-splitter (fragment-order packed bf16) ----
__global__ void pack_weights(const float* __restrict__ Wp, const float* __restrict__ Wq,
        const float* __restrict__ Wk, const float* __restrict__ Wv, const float* __restrict__ Wo,
        const float* __restrict__ Wu, const float* __restrict__ Wf1, const float* __restrict__ Wf2,
        const float* __restrict__ Wa, const float* __restrict__ Wout)
{
    const float* src[24]; int Js[24]; long base[24]; int ents[24];
    int n = 0; long off = 0;
    #define ADDSEG(w, K_, J_) { src[n]=(w); Js[n]=(J_); ents[n]=(K_)*(J_)/4; base[n]=off; off+=(K_)*(J_)/4; n++; }
    ADDSEG(Wp, 256, 1024);
    for (int l = 0; l < 3; l++) {
        ADDSEG(Wq+l*16384,128,128); ADDSEG(Wk+l*16384,128,128); ADDSEG(Wv+l*16384,128,128);
        ADDSEG(Wo+l*16384,128,128); ADDSEG(Wu+l*32768,256,128);
        ADDSEG(Wf1+l*65536,128,512); ADDSEG(Wf2+l*65536,512,128);
    }
    ADDSEG(Wa,1024,128); ADDSEG(Wout,128,128);
    #undef ADDSEG

    for (long idx = blockIdx.x*(long)blockDim.x + threadIdx.x; idx < PK_TOTAL;
         idx += (long)gridDim.x * blockDim.x) {
        int s = 0;
        while (s < 23 && idx >= base[s] + ents[s]) s++;
        long e = idx - base[s];
        const float* W = src[s]; const int J = Js[s];
        int lane = (int)(e & 31);
        long tmp = e >> 5;
        int jt  = (int)(tmp % (J/8));
        int k16 = (int)(tmp / (J/8));
        int tid = lane & 3, group = lane >> 2;
        int j  = jt*8 + group;
        int k0 = k16*16 + 2*tid;
        float w0 = W[(size_t)(k0  )*J + j];
        float w1 = W[(size_t)(k0+1)*J + j];
        float w2 = W[(size_t)(k0+8)*J + j];
        float w3 = W[(size_t)(k0+9)*J + j];
        unsigned bh0, bl0, bh1, bl1;
        split_bf16(w0, w1, bh0, bl0);
        split_bf16(w2, w3, bh1, bl1);
        g_packed[idx] = make_uint4(bh0, bh1, bl0, bl1);
    }
}

// Tensor-core GEMM: A pre-split in smem (u32 window-permuted), B pre-split packed in global.
template<int M,int K,int J,int K2,int MI,int EPI,bool OSPLIT,
         int KI16=1<<28,int LDKW=0,int JI=1<<28,int SJ=0>
__device__ __forceinline__ void mma_gemm(
    const unsigned* __restrict__ A,  int lda,
    const unsigned* __restrict__ A2, int lda2,
    const uint4* __restrict__ Wpk,
    const float* __restrict__ bias,
    void* __restrict__ outp, int s_in, int s_out)
{
    constexpr int TM16   = (M + 15) / 16;
    constexpr int TJ8    = J / 8;
    constexpr int NWARP  = NT / 32;
    static_assert((TM16 * TJ8) % NWARP == 0, "tile count must divide warps");
    constexpr int NT_S   = TM16 * TJ8 / NWARP;
    constexpr int TJSTEP = NWARP / TM16;
    constexpr bool PRED  = (M % 16) != 0;

    const int w     = threadIdx.x >> 5;
    const int lane  = threadIdx.x & 31;
    const int group = lane >> 2;
    const int tid   = lane & 3;
    const int tm    = w % TM16;
    const int tj0   = w / TM16;
    const int r0    = tm * 16 + group;
    const int r1    = r0 + 8;

    const uint4* wp = Wpk + tj0 * 32 + lane;
    const unsigned* Ar0 = A + r0 * lda + tid * 4;
    const unsigned* Ar1 = A + r1 * lda + tid * 4;

    float acc[NT_S][4];
    #pragma unroll
    for (int s = 0; s < NT_S; s++) { acc[s][0]=0.f; acc[s][1]=0.f; acc[s][2]=0.f; acc[s][3]=0.f; }

    #define K_BODY(IIEXPR) {                                                   \
        const int woff = ((IIEXPR) / KI16) * LDKW + ((IIEXPR) % KI16) * 16;    \
        uint4 a0, a1;                                                          \
        if (!PRED || r0 < M) a0 = *(const uint4*)(Ar0 + woff); else a0 = make_uint4(0,0,0,0); \
        if (!PRED || r1 < M) a1 = *(const uint4*)(Ar1 + woff); else a1 = make_uint4(0,0,0,0); \
        unsigned ah[4] = {a0.x, a1.x, a0.z, a1.z};                             \
        unsigned al[4] = {a0.y, a1.y, a0.w, a1.w};                             \
        _Pragma("unroll")                                                      \
        for (int s = 0; s < NT_S; s++) {                                       \
            uint4 b = wp[s * TJSTEP * 32];                                     \
            unsigned bh[2] = {b.x, b.y}, bl[2] = {b.z, b.w};                   \
            mma_bf16(acc[s], ah, bh);                                          \
            mma_bf16(acc[s], ah, bl);                                          \
            mma_bf16(acc[s], al, bh);                                          \
        }                                                                      \
        wp += TJ8 * 32;                                                        \
    }

    if constexpr (K/16 <= 8) {
        #pragma unroll
        for (int ii = 0; ii < K/16; ii++) K_BODY(ii)
    } else {
        #pragma unroll 2
        for (int ii = 0; ii < K/16; ii++) K_BODY(ii)
    }
    if constexpr (K2 > 0) {
        const unsigned* B0 = A2 + r0 * lda2 + tid * 4;
        const unsigned* B1 = A2 + r1 * lda2 + tid * 4;
        #define K2_BODY(II) {                                                  \
            uint4 a0 = *(const uint4*)(B0 + (II) * 16);                        \
            uint4 a1 = *(const uint4*)(B1 + (II) * 16);                        \
            unsigned ah[4] = {a0.x, a1.x, a0.z, a1.z};                         \
            unsigned al[4] = {a0.y, a1.y, a0.w, a1.w};                         \
            _Pragma("unroll")                                                  \
            for (int s = 0; s < NT_S; s++) {                                   \
                uint4 b = wp[s * TJSTEP * 32];                                 \
                unsigned bh[2] = {b.x, b.y}, bl[2] = {b.z, b.w};               \
                mma_bf16(acc[s], ah, bh);                                      \
                mma_bf16(acc[s], ah, bl);                                      \
                mma_bf16(acc[s], al, bh);                                      \
            }                                                                  \
            wp += TJ8 * 32;                                                    \
        }
        if constexpr (K2/16 <= 8) {
            #pragma unroll
            for (int ii = 0; ii < K2/16; ii++) K2_BODY(ii)
        } else {
            #pragma unroll 2
            for (int ii = 0; ii < K2/16; ii++) K2_BODY(ii)
        }
        #undef K2_BODY
    }
    #undef K_BODY

    // epilogue
    #pragma unroll
    for (int s = 0; s < NT_S; s++) {
        const int j0 = (tj0 + s * TJSTEP) * 8;
        const int c0 = j0 + 2 * tid;
        const float b0 = bias[c0], b1 = bias[c0 + 1];
        float v00 = acc[s][0] + b0, v01 = acc[s][1] + b1;
        float v10 = acc[s][2] + b0, v11 = acc[s][3] + b1;
        if constexpr (EPI == EPI_GELU) { v00=gelu_f(v00); v01=gelu_f(v01); v10=gelu_f(v10); v11=gelu_f(v11); }
        if constexpr (OSPLIT) {
            unsigned* ob = (unsigned*)outp;
            const int off = (c0 >> 4) * 16 + tid * 4 + ((j0 >> 3) & 1) * 2;
            if (!PRED || r0 < M) {
                unsigned hi, lo; split_bf16(v00, v01, hi, lo);
                *(uint2*)(ob + r0 * s_in + off) = make_uint2(hi, lo);
            }
            if (!PRED || r1 < M) {
                unsigned hi, lo; split_bf16(v10, v11, hi, lo);
                *(uint2*)(ob + r1 * s_in + off) = make_uint2(hi, lo);
            }
        } else {
            float* of = (float*)outp;
            const int jo = (c0 / JI) * SJ + (c0 % JI);
            if (!PRED || r0 < M) {
                float* p = of + (r0 % MI) * s_in + (r0 / MI) * s_out + jo;
                if constexpr (EPI == EPI_ADD)      { p[0] += v00; p[1] += v01; }
                else if constexpr (EPI == EPI_RELU_ADD) { p[0] += fmaxf(v00,0.f); p[1] += fmaxf(v01,0.f); }
                else { p[0] = v00; p[1] = v01; }
            }
            if (!PRED || r1 < M) {
                float* p = of + (r1 % MI) * s_in + (r1 / MI) * s_out + jo;
                if constexpr (EPI == EPI_ADD)      { p[0] += v10; p[1] += v11; }
                else if constexpr (EPI == EPI_RELU_ADD) { p[0] += fmaxf(v10,0.f); p[1] += fmaxf(v11,0.f); }
                else { p[0] = v10; p[1] = v11; }
            }
        }
    }
}

// LayerNorm over 128 elems; lane owns 4 consecutive elems; writes split format.
__device__ __forceinline__ void ln_split(const float* __restrict__ src, unsigned* __restrict__ dst,
                                         const float* __restrict__ g, const float* __restrict__ b)
{
    const int lane = threadIdx.x & 31;
    float4 v = *(const float4*)(src + lane * 4);
    float s  = v.x + v.y + v.z + v.w;
    float sq = v.x*v.x + v.y*v.y + v.z*v.z + v.w*v.w;
    #pragma unroll
    for (int o = 16; o > 0; o >>= 1) {
        s  += __shfl_xor_sync(0xffffffffu, s,  o);
        sq += __shfl_xor_sync(0xffffffffu, sq, o);
    }
    float mean = s * (1.f/128.f);
    float rstd = rsqrtf(sq * (1.f/128.f) - mean*mean + 1e-5f);
    float4 gg = *(const float4*)(g + lane * 4);
    float4 bb = *(const float4*)(b + lane * 4);
    float y0 = (v.x-mean)*rstd*gg.x + bb.x;
    float y1 = (v.y-mean)*rstd*gg.y + bb.y;
    float y2 = (v.z-mean)*rstd*gg.z + bb.z;
    float y3 = (v.w-mean)*rstd*gg.w + bb.w;
    const int w  = lane >> 2;
    const int p0 = (lane & 3) * 2;
    store_split_pair(dst, w, p0,     y0, y1);
    store_split_pair(dst, w, p0 + 1, y2, y3);
}

__global__ void __launch_bounds__(NT, 1) fused_reasoner(
    const float* __restrict__ x,
    const float* __restrict__ bp,
    const float* __restrict__ ln1_g, const float* __restrict__ ln1_b,
    const float* __restrict__ bq, const float* __restrict__ bk,
    const float* __restrict__ bv, const float* __restrict__ bo,
    const float* __restrict__ bu,
    const float* __restrict__ ln2_g, const float* __restrict__ ln2_b,
    const float* __restrict__ bf1, const float* __restrict__ bf2,
    const float* __restrict__ ba, const float* __restrict__ bout,
    float* __restrict__ out)
{
    extern __shared__ unsigned SU[];
    float* Sf = (float*)SU;
    const int t = threadIdx.x;
    const int wid = t >> 5;            // 0..15
    const int row0 = blockIdx.x * ROWS;

    // ---- stage x tile (8 rows x 256) into split format at SP2 (stride 272) ----
    for (int idx = t; idx < 1024; idx += NT) {          // 8*128 pairs
        int nr = idx >> 7, pr = idx & 127;
        float2 xv = *(const float2*)(x + (size_t)(row0 + nr) * 256 + 2 * pr);
        store_split_pair(SU + OFF_SP2 + nr * 272, pr >> 3, pr & 7, xv.x, xv.y);
    }
    __syncthreads();
    // h = x @ Wp + bp (fp32 H; col j -> node j/128 col j%128)
    mma_gemm<8,256,1024,0,8,EPI_STORE,false, (1<<28),0, 128,LDH>(
        SU+OFF_SP2,272, nullptr,0, g_packed+PK_WP, bp, Sf+OFF_H, 8*LDH, 0);
    __syncthreads();

    #pragma unroll 1
    for (int l = 0; l < 3; l++) {
        const uint4* pkl = g_packed + PK_L0 + (long)l * PK_LSTR;
        const float* g1 = ln1_g + l*128;   const float* b1 = ln1_b + l*128;
        const float* g2 = ln2_g + l*128;   const float* b2 = ln2_b + l*128;

        // ---- LN1 -> hn split (SP1, stride 144) ----
        #pragma unroll
        for (int it = 0; it < 4; it++) {
            int p = it * 16 + wid;
            ln_split(Sf + OFF_H + p*LDH, SU + OFF_SP1 + p*144, g1, b1);
        }
        __syncthreads();

        // ---- Q,K,V projections (fp32 outs) ----
        mma_gemm<64,128,128,0,64,EPI_STORE,false>(SU+OFF_SP1,144, nullptr,0, pkl+PK_WQ, bq+l*128, Sf+OFF_QA, LDH, 0);
        mma_gemm<64,128,128,0,64,EPI_STORE,false>(SU+OFF_SP1,144, nullptr,0, pkl+PK_WK, bk+l*128, Sf+OFF_FK, LDH, 0);
        mma_gemm<64,128,128,0,64,EPI_STORE,false>(SU+OFF_SP1,144, nullptr,0, pkl+PK_WV, bv+l*128, Sf+OFF_FV, LDH, 0);
        __syncthreads();

        // ---- causal attention on ALL 512 threads: (row, node, head, d-half) ----
        {
            const int r  = t >> 6;
            const int n  = (t >> 3) & 7;
            const int h  = (t >> 1) & 3;
            const int dh = t & 1;
            const float* qp = Sf + OFF_QA + (r*8 + n)*LDH + h*32 + dh*16;
            float pr8[8];
            // all 8 dots computed unconditionally -> warp-uniform shfl
            #pragma unroll
            for (int m = 0; m < 8; m++) {
                const float* kp = Sf + OFF_FK + (r*8 + m)*LDH + h*32 + dh*16;
                float sc = 0.f;
                #pragma unroll
                for (int d = 0; d < 16; d++) sc += qp[d] * kp[d];
                sc += __shfl_xor_sync(0xffffffffu, sc, 1);
                pr8[m] = sc * 0.17677669529663688f;
            }
            float mx = -1e30f;
            #pragma unroll
            for (int m = 0; m < 8; m++) if (m <= n) mx = fmaxf(mx, pr8[m]);
            float sum = 0.f;
            #pragma unroll
            for (int m = 0; m < 8; m++) {
                pr8[m] = (m <= n) ? __expf(pr8[m] - mx) : 0.f;
                sum += pr8[m];
            }
            const float inv = 1.f / sum;
            __syncthreads();   // all Q reads done before split overwrite
            float o[16];
            #pragma unroll
            for (int d = 0; d < 16; d++) {
                float acc = 0.f;
                #pragma unroll
                for (int m = 0; m < 8; m++)
                    acc += pr8[m] * (Sf + OFF_FV)[(r*8 + m)*LDH + h*32 + dh*16 + d];
                o[d] = acc * inv;
            }
            unsigned* ad = SU + OFF_QA + (r*8 + n)*144 + h*32 + dh*16;
            #pragma unroll
            for (int i = 0; i < 8; i++)
                store_split_pair(ad, 0, i, o[2*i], o[2*i+1]);
        }
        __syncthreads();

        // ---- attO = att @ Wo + bo -> split (SP2, 144) ----
        mma_gemm<64,128,128,0,64,EPI_STORE,true>(SU+OFF_QA,144, nullptr,0, pkl+PK_WO, bo+l*128, SU+OFF_SP2, 144, 0);
        __syncthreads();

        // ---- h += relu( [hn | attO] @ Wu + bu )  (fp32 H) ----
        mma_gemm<64,128,128,128,64,EPI_RELU_ADD,false>(SU+OFF_SP1,144, SU+OFF_SP2,144, pkl+PK_WU, bu+l*128, Sf+OFF_H, LDH, 0);
        __syncthreads();

        // ---- FFN in 2 chunks of 4 nodes; mid split 32x528 overlays FK+FV ----
        #pragma unroll 1
        for (int c = 0; c < 2; c++) {
            #pragma unroll
            for (int it = 0; it < 2; it++) {
                int p = it * 16 + wid;            // 0..31 = (r*4 + nn)
                int r = p >> 2, nn = p & 3;
                ln_split(Sf + OFF_H + (r*8 + c*4 + nn)*LDH, SU + OFF_QA + p*144, g2, b2);
            }
            __syncthreads();
            mma_gemm<32,128,512,0,32,EPI_GELU,true>(SU+OFF_QA,144, nullptr,0, pkl+PK_WF1, bf1+l*512, SU+OFF_FK, 528, 0);
            __syncthreads();
            mma_gemm<32,512,128,0,4,EPI_ADD,false>(SU+OFF_FK,528, nullptr,0, pkl+PK_WF2, bf2+l*128,
                                                   Sf+OFF_H + c*4*LDH, LDH, 8*LDH);
            __syncthreads();
        }
    }

    // ---- convert H -> splitH (SP1: batch stride 1168, node stride 144) ----
    for (int idx = t; idx < 4096; idx += NT) {          // 64 rows x 64 pairs
        int nr = idx >> 6, pr = idx & 63;
        float2 hv = *(const float2*)(Sf + OFF_H + nr*LDH + 2*pr);
        store_split_pair(SU + OFF_SP1 + (nr >> 3) * 1168 + (nr & 7) * 144, pr >> 3, pr & 7, hv.x, hv.y);
    }
    __syncthreads();
    // agg = gelu(flat @ Wa + ba) -> split (SP2, 144)
    mma_gemm<8,1024,128,0,8,EPI_GELU,true, 8,144>(SU+OFF_SP1,1168, nullptr,0, g_packed+PK_WA, ba, SU+OFF_SP2, 144, 0);
    __syncthreads();
    // out = agg @ Wout + bout (global fp32)
    mma_gemm<8,128,128,0,8,EPI_STORE,false>(SU+OFF_SP2,144, nullptr,0, g_packed+PK_WOUT, bout,
                                            out + (size_t)row0*128, 128, 0);
}

extern "C" void kernel_launch(void* const* d_in, const int* in_sizes, int n_in,
                              void* d_out, int out_size)
{
    (void)n_in; (void)out_size;
    const float* x     = (const float*)d_in[0];
    const float* Wp    = (const float*)d_in[1];
    const float* bp    = (const float*)d_in[2];
    const float* ln1_g = (const float*)d_in[3];
    const float* ln1_b = (const float*)d_in[4];
    const float* Wq    = (const float*)d_in[5];
    const float* bq    = (const float*)d_in[6];
    const float* Wk    = (const float*)d_in[7];
    const float* bk    = (const float*)d_in[8];
    const float* Wv    = (const float*)d_in[9];
    const float* bv    = (const float*)d_in[10];
    const float* Wo    = (const float*)d_in[11];
    const float* bo    = (const float*)d_in[12];
    const float* Wu    = (const float*)d_in[13];
    const float* bu    = (const float*)d_in[14];
    const float* ln2_g = (const float*)d_in[15];
    const float* ln2_b = (const float*)d_in[16];
    const float* Wf1   = (const float*)d_in[17];
    const float* bf1   = (const float*)d_in[18];
    const float* Wf2   = (const float*)d_in[19];
    const float* bf2   = (const float*)d_in[20];
    const float* Wa    = (const float*)d_in[21];
    const float* ba    = (const float*)d_in[22];
    const float* Wout  = (const float*)d_in[23];
    const float* bout  = (const float*)d_in[24];

    const int Bsz = in_sizes[0] / 256;       // DIN = 256
    const int grid = Bsz / ROWS;
    const size_t smem = SMEM_U32 * sizeof(unsigned);

    pack_weights<<<1072, 256>>>(Wp, Wq, Wk, Wv, Wo, Wu, Wf1, Wf2, Wa, Wout);

    cudaFuncSetAttribute(fused_reasoner, cudaFuncAttributeMaxDynamicSharedMemorySize, (int)smem);
    fused_reasoner<<<grid, NT, smem>>>(
        x, bp, ln1_g, ln1_b, bq, bk, bv, bo, bu, ln2_g, ln2_b,
        bf1, bf2, ba, bout, (float*)d_out);
}

// round 15
// speedup vs baseline: 1.0564x; 1.0564x over previous
#include <cuda_runtime.h>
#include <math.h>

#define NT 512
#define ROWS 8
#define LDH 132            // fp32 H row stride (132%32==4)

// ---- smem regions (u32 units) ----
#define OFF_H    0         // H fp32: 64 x 132 = 8448
#define OFF_SP1  8448      // hn split 64x144=9216 / splitH 8x1168=9344
#define OFF_Q    17792     // Q fp32 64x132 / att split 64x144 / hn2 split 32x144   (9216)
#define OFF_K    27008     // K fp32 64x132; FFN mid split 32x528 starts here       (9216)
#define OFF_V    36224     // V fp32 64x132                                         (9216)
#define OFF_SP2  45440     // x split 8x272 / attO split 64x144 / agg split 8x144  (9216)
#define SMEM_U32 54656     // 218,624 bytes

// ---- packed (pre-split bf16) weight scratch: uint4{bh0,bh1,bl0,bl1} per [k16][jt][lane] ----
#define PK_WP     0
#define PK_L0     65536
#define PK_LSTR   57344
#define PK_WQKV   0          // combined J=384: jt 0-15 Q, 16-31 K, 32-47 V (12288)
#define PK_WO     12288
#define PK_WU     16384
#define PK_WF1    24576
#define PK_WF2    40960
#define PK_WA     237568
#define PK_WOUT   270336
#define PK_TOTAL  274432

__device__ uint4 g_packed[PK_TOTAL];
__device__ float g_bqkv[3 * 384];   // per-layer concatenated {bq|bk|bv}

enum { EPI_STORE=0, EPI_GELU=2, EPI_ADD=3, EPI_RELU_ADD=4 };

__device__ __forceinline__ float gelu_f(float v) {
    return 0.5f * v * (1.0f + erff(v * 0.70710678118654752440f));
}

// ---- bf16 mma helpers ----
__device__ __forceinline__ void mma_bf16(float* d, const unsigned* a, const unsigned* b) {
    asm("mma.sync.aligned.m16n8k16.row.col.f32.bf16.bf16.f32 "
        "{%0,%1,%2,%3}, {%4,%5,%6,%7}, {%8,%9}, {%0,%1,%2,%3};"
        : "+f"(d[0]), "+f"(d[1]), "+f"(d[2]), "+f"(d[3])
        : "r"(a[0]), "r"(a[1]), "r"(a[2]), "r"(a[3]), "r"(b[0]), "r"(b[1]));
}
__device__ __forceinline__ unsigned cvt_bf16x2(float hi_elem, float lo_elem) {
    unsigned r;
    asm("cvt.rn.bf16x2.f32 %0, %1, %2;" : "=r"(r) : "f"(hi_elem), "f"(lo_elem));
    return r;
}
__device__ __forceinline__ float bf_lo(unsigned r) { return __uint_as_float(r << 16); }
__device__ __forceinline__ float bf_hi(unsigned r) { return __uint_as_float(r & 0xFFFF0000u); }
__device__ __forceinline__ void split_bf16(float x, float y, unsigned& hi, unsigned& lo) {
    hi = cvt_bf16x2(y, x);
    lo = cvt_bf16x2(y - bf_hi(hi), x - bf_lo(hi));
}
__device__ __forceinline__ int pslot(int p) { return (p < 4) ? p * 4 : (p - 4) * 4 + 2; }
__device__ __forceinline__ void store_split_pair(unsigned* row, int w, int p, float x, float y) {
    unsigned hi, lo; split_bf16(x, y, hi, lo);
    *(uint2*)(row + w * 16 + pslot(p)) = make_uint2(hi, lo);
}

// ---- weight pre-splitter (fragment-order packed bf16); QKV column-concatenated ----
__global__ void pack_weights(const float* __restrict__ Wp, const float* __restrict__ Wq,
        const float* __restrict__ Wk, const float* __restrict__ Wv, const float* __restrict__ Wo,
        const float* __restrict__ Wu, const float* __restrict__ Wf1, const float* __restrict__ Wf2,
        const float* __restrict__ Wa, const float* __restrict__ Wout,
        const float* __restrict__ bq, const float* __restrict__ bk, const float* __restrict__ bv)
{
    const float* src[20]; const float* srcK[20]; const float* srcV[20];
    int Js[20]; long base[20]; int ents[20];
    int n = 0; long off = 0;
    #define ADDSEG(w, K_, J_) { src[n]=(w); srcK[n]=nullptr; srcV[n]=nullptr; Js[n]=(J_); \
                                ents[n]=(K_)*(J_)/4; base[n]=off; off+=(K_)*(J_)/4; n++; }
    #define ADDSEG3(wa_, wb_, wc_, K_) { src[n]=(wa_); srcK[n]=(wb_); srcV[n]=(wc_); Js[n]=384; \
                                ents[n]=(K_)*384/4; base[n]=off; off+=(K_)*384/4; n++; }
    ADDSEG(Wp, 256, 1024);
    for (int l = 0; l < 3; l++) {
        ADDSEG3(Wq+l*16384, Wk+l*16384, Wv+l*16384, 128);
        ADDSEG(Wo+l*16384,128,128); ADDSEG(Wu+l*32768,256,128);
        ADDSEG(Wf1+l*65536,128,512); ADDSEG(Wf2+l*65536,512,128);
    }
    ADDSEG(Wa,1024,128); ADDSEG(Wout,128,128);
    #undef ADDSEG
    #undef ADDSEG3
    // n == 18 segments

    for (long idx = blockIdx.x*(long)blockDim.x + threadIdx.x; idx < PK_TOTAL + 1152;
         idx += (long)gridDim.x * blockDim.x) {
        if (idx >= PK_TOTAL) {   // combined QKV biases
            int e = (int)(idx - PK_TOTAL);
            int l = e / 384, j = e % 384;
            const float* b = (j < 128) ? bq : (j < 256) ? bk : bv;
            g_bqkv[e] = b[l*128 + (j & 127)];
            continue;
        }
        int s = 0;
        while (s < 17 && idx >= base[s] + ents[s]) s++;
        long e = idx - base[s];
        const int J = Js[s];
        int lane = (int)(e & 31);
        long tmp = e >> 5;
        int jt  = (int)(tmp % (J/8));
        int k16 = (int)(tmp / (J/8));
        int tid = lane & 3, group = lane >> 2;
        int j  = jt*8 + group;
        int k0 = k16*16 + 2*tid;
        const float* Ws; int jj, ld;
        if (srcK[s]) {
            Ws = (j < 128) ? src[s] : (j < 256) ? srcK[s] : srcV[s];
            jj = j & 127; ld = 128;
        } else {
            Ws = src[s]; jj = j; ld = J;
        }
        float w0 = Ws[(size_t)(k0  )*ld + jj];
        float w1 = Ws[(size_t)(k0+1)*ld + jj];
        float w2 = Ws[(size_t)(k0+8)*ld + jj];
        float w3 = Ws[(size_t)(k0+9)*ld + jj];
        unsigned bh0, bl0, bh1, bl1;
        split_bf16(w0, w1, bh0, bl0);
        split_bf16(w2, w3, bh1, bl1);
        g_packed[idx] = make_uint4(bh0, bh1, bl0, bl1);
    }
}

// Tensor-core GEMM: A pre-split in smem (u32 window-permuted), B pre-split packed in global.
template<int M,int K,int J,int K2,int MI,int EPI,bool OSPLIT,
         int KI16=1<<28,int LDKW=0,int JI=1<<28,int SJ=0>
__device__ __forceinline__ void mma_gemm(
    const unsigned* __restrict__ A,  int lda,
    const unsigned* __restrict__ A2, int lda2,
    const uint4* __restrict__ Wpk,
    const float* __restrict__ bias,
    void* __restrict__ outp, int s_in, int s_out)
{
    constexpr int TM16   = (M + 15) / 16;
    constexpr int TJ8    = J / 8;
    constexpr int NWARP  = NT / 32;
    static_assert((TM16 * TJ8) % NWARP == 0, "tile count must divide warps");
    constexpr int NT_S   = TM16 * TJ8 / NWARP;
    constexpr int TJSTEP = NWARP / TM16;
    constexpr bool PRED  = (M % 16) != 0;

    const int w     = threadIdx.x >> 5;
    const int lane  = threadIdx.x & 31;
    const int group = lane >> 2;
    const int tid   = lane & 3;
    const int tm    = w % TM16;
    const int tj0   = w / TM16;
    const int r0    = tm * 16 + group;
    const int r1    = r0 + 8;

    const uint4* wp = Wpk + tj0 * 32 + lane;
    const unsigned* Ar0 = A + r0 * lda + tid * 4;
    const unsigned* Ar1 = A + r1 * lda + tid * 4;

    float acc[NT_S][4];
    #pragma unroll
    for (int s = 0; s < NT_S; s++) { acc[s][0]=0.f; acc[s][1]=0.f; acc[s][2]=0.f; acc[s][3]=0.f; }

    #pragma unroll 2
    for (int ii = 0; ii < K/16; ii++) {
        const int woff = (ii / KI16) * LDKW + (ii % KI16) * 16;
        uint4 a0, a1;
        if (!PRED || r0 < M) a0 = *(const uint4*)(Ar0 + woff); else a0 = make_uint4(0,0,0,0);
        if (!PRED || r1 < M) a1 = *(const uint4*)(Ar1 + woff); else a1 = make_uint4(0,0,0,0);
        unsigned ah[4] = {a0.x, a1.x, a0.z, a1.z};
        unsigned al[4] = {a0.y, a1.y, a0.w, a1.w};
        #pragma unroll
        for (int s = 0; s < NT_S; s++) {
            uint4 b = wp[s * TJSTEP * 32];
            unsigned bh[2] = {b.x, b.y}, bl[2] = {b.z, b.w};
            mma_bf16(acc[s], ah, bh);
            mma_bf16(acc[s], ah, bl);
            mma_bf16(acc[s], al, bh);
        }
        wp += TJ8 * 32;
    }
    if constexpr (K2 > 0) {
        const unsigned* B0 = A2 + r0 * lda2 + tid * 4;
        const unsigned* B1 = A2 + r1 * lda2 + tid * 4;
        #pragma unroll 2
        for (int ii = 0; ii < K2/16; ii++) {
            uint4 a0 = *(const uint4*)(B0 + ii * 16);
            uint4 a1 = *(const uint4*)(B1 + ii * 16);
            unsigned ah[4] = {a0.x, a1.x, a0.z, a1.z};
            unsigned al[4] = {a0.y, a1.y, a0.w, a1.w};
            #pragma unroll
            for (int s = 0; s < NT_S; s++) {
                uint4 b = wp[s * TJSTEP * 32];
                unsigned bh[2] = {b.x, b.y}, bl[2] = {b.z, b.w};
                mma_bf16(acc[s], ah, bh);
                mma_bf16(acc[s], ah, bl);
                mma_bf16(acc[s], al, bh);
            }
            wp += TJ8 * 32;
        }
    }

    // epilogue
    #pragma unroll
    for (int s = 0; s < NT_S; s++) {
        const int j0 = (tj0 + s * TJSTEP) * 8;
        const int c0 = j0 + 2 * tid;
        const float b0 = bias[c0], b1 = bias[c0 + 1];
        float v00 = acc[s][0] + b0, v01 = acc[s][1] + b1;
        float v10 = acc[s][2] + b0, v11 = acc[s][3] + b1;
        if constexpr (EPI == EPI_GELU) { v00=gelu_f(v00); v01=gelu_f(v01); v10=gelu_f(v10); v11=gelu_f(v11); }
        if constexpr (OSPLIT) {
            unsigned* ob = (unsigned*)outp;
            const int off = (c0 >> 4) * 16 + tid * 4 + ((j0 >> 3) & 1) * 2;
            if (!PRED || r0 < M) {
                unsigned hi, lo; split_bf16(v00, v01, hi, lo);
                *(uint2*)(ob + r0 * s_in + off) = make_uint2(hi, lo);
            }
            if (!PRED || r1 < M) {
                unsigned hi, lo; split_bf16(v10, v11, hi, lo);
                *(uint2*)(ob + r1 * s_in + off) = make_uint2(hi, lo);
            }
        } else {
            float* of = (float*)outp;
            const int jo = (c0 / JI) * SJ + (c0 % JI);
            if (!PRED || r0 < M) {
                float* p = of + (r0 % MI) * s_in + (r0 / MI) * s_out + jo;
                if constexpr (EPI == EPI_ADD)      { p[0] += v00; p[1] += v01; }
                else if constexpr (EPI == EPI_RELU_ADD) { p[0] += fmaxf(v00,0.f); p[1] += fmaxf(v01,0.f); }
                else { p[0] = v00; p[1] = v01; }
            }
            if (!PRED || r1 < M) {
                float* p = of + (r1 % MI) * s_in + (r1 / MI) * s_out + jo;
                if constexpr (EPI == EPI_ADD)      { p[0] += v10; p[1] += v11; }
                else if constexpr (EPI == EPI_RELU_ADD) { p[0] += fmaxf(v10,0.f); p[1] += fmaxf(v11,0.f); }
                else { p[0] = v10; p[1] = v11; }
            }
        }
    }
}

// LayerNorm over 128 elems; lane owns 4 consecutive elems; writes split format.
__device__ __forceinline__ void ln_split(const float* __restrict__ src, unsigned* __restrict__ dst,
                                         const float* __restrict__ g, const float* __restrict__ b)
{
    const int lane = threadIdx.x & 31;
    float4 v = *(const float4*)(src + lane * 4);
    float s  = v.x + v.y + v.z + v.w;
    float sq = v.x*v.x + v.y*v.y + v.z*v.z + v.w*v.w;
    #pragma unroll
    for (int o = 16; o > 0; o >>= 1) {
        s  += __shfl_xor_sync(0xffffffffu, s,  o);
        sq += __shfl_xor_sync(0xffffffffu, sq, o);
    }
    float mean = s * (1.f/128.f);
    float rstd = rsqrtf(sq * (1.f/128.f) - mean*mean + 1e-5f);
    float4 gg = *(const float4*)(g + lane * 4);
    float4 bb = *(const float4*)(b + lane * 4);
    float y0 = (v.x-mean)*rstd*gg.x + bb.x;
    float y1 = (v.y-mean)*rstd*gg.y + bb.y;
    float y2 = (v.z-mean)*rstd*gg.z + bb.z;
    float y3 = (v.w-mean)*rstd*gg.w + bb.w;
    const int w  = lane >> 2;
    const int p0 = (lane & 3) * 2;
    store_split_pair(dst, w, p0,     y0, y1);
    store_split_pair(dst, w, p0 + 1, y2, y3);
}

__global__ void __launch_bounds__(NT, 1) fused_reasoner(
    const float* __restrict__ x,
    const float* __restrict__ bp,
    const float* __restrict__ ln1_g, const float* __restrict__ ln1_b,
    const float* __restrict__ bo, const float* __restrict__ bu,
    const float* __restrict__ ln2_g, const float* __restrict__ ln2_b,
    const float* __restrict__ bf1, const float* __restrict__ bf2,
    const float* __restrict__ ba, const float* __restrict__ bout,
    float* __restrict__ out)
{
    extern __shared__ unsigned SU[];
    float* Sf = (float*)SU;
    const int t = threadIdx.x;
    const int wid = t >> 5;            // 0..15
    const int row0 = blockIdx.x * ROWS;

    // ---- stage x tile (8 rows x 256) into split format at SP2 (stride 272) ----
    for (int idx = t; idx < 1024; idx += NT) {          // 8*128 pairs
        int nr = idx >> 7, pr = idx & 127;
        float2 xv = *(const float2*)(x + (size_t)(row0 + nr) * 256 + 2 * pr);
        store_split_pair(SU + OFF_SP2 + nr * 272, pr >> 3, pr & 7, xv.x, xv.y);
    }
    __syncthreads();
    // h = x @ Wp + bp (fp32 H; col j -> node j/128 col j%128)
    mma_gemm<8,256,1024,0,8,EPI_STORE,false, (1<<28),0, 128,LDH>(
        SU+OFF_SP2,272, nullptr,0, g_packed+PK_WP, bp, Sf+OFF_H, 8*LDH, 0);
    __syncthreads();

    #pragma unroll 1
    for (int l = 0; l < 3; l++) {
        const uint4* pkl = g_packed + PK_L0 + (long)l * PK_LSTR;
        const float* g1 = ln1_g + l*128;   const float* b1 = ln1_b + l*128;
        const float* g2 = ln2_g + l*128;   const float* b2 = ln2_b + l*128;

        // ---- LN1 -> hn split (SP1, stride 144) ----
        #pragma unroll
        for (int it = 0; it < 4; it++) {
            int p = it * 16 + wid;
            ln_split(Sf + OFF_H + p*LDH, SU + OFF_SP1 + p*144, g1, b1);
        }
        __syncthreads();

        // ---- fused Q|K|V projection (J=384; col j -> buffer j/128 @ stride 9216) ----
        mma_gemm<64,128,384,0,64,EPI_STORE,false, (1<<28),0, 128,9216>(
            SU+OFF_SP1,144, nullptr,0, pkl+PK_WQKV, g_bqkv + l*384, Sf+OFF_Q, LDH, 0);
        __syncthreads();

        // ---- causal attention: thread = (row, head, query-node); 256 of 512 threads ----
        float pr8[8]; float inv = 0.f;
        int ar, ahd, an;
        if (t < 256) {
            ar = t >> 5; ahd = (t >> 3) & 3; an = t & 7;
            const float* qp = Sf + OFF_Q + (ar*8 + an)*LDH + ahd*32;
            float mx = -1e30f;
            #pragma unroll
            for (int m = 0; m < 8; m++) {
                if (m <= an) {
                    const float* kp = Sf + OFF_K + (ar*8 + m)*LDH + ahd*32;
                    float sc = 0.f;
                    #pragma unroll
                    for (int d = 0; d < 32; d++) sc += qp[d] * kp[d];
                    sc *= 0.17677669529663688f;
                    pr8[m] = sc;
                    mx = fmaxf(mx, sc);
                }
            }
            float sum = 0.f;
            #pragma unroll
            for (int m = 0; m < 8; m++) if (m <= an) { pr8[m] = __expf(pr8[m] - mx); sum += pr8[m]; }
            inv = 1.f / sum;
        }
        __syncthreads();   // all Q reads done before split overwrite
        if (t < 256) {
            float o[32];
            #pragma unroll
            for (int d = 0; d < 32; d++) {
                float acc = 0.f;
                #pragma unroll
                for (int m = 0; m < 8; m++)
                    if (m <= an) acc += pr8[m] * (Sf + OFF_V)[(ar*8 + m)*LDH + ahd*32 + d];
                o[d] = acc * inv;
            }
            unsigned* ad = SU + OFF_Q + (ar*8 + an)*144 + ahd*32;
            #pragma unroll
            for (int i = 0; i < 16; i++)
                store_split_pair(ad, i >> 3, i & 7, o[2*i], o[2*i+1]);
        }
        __syncthreads();

        // ---- attO = att @ Wo + bo -> split (SP2, 144) ----
        mma_gemm<64,128,128,0,64,EPI_STORE,true>(SU+OFF_Q,144, nullptr,0, pkl+PK_WO, bo+l*128, SU+OFF_SP2, 144, 0);
        __syncthreads();

        // ---- h += relu( [hn | attO] @ Wu + bu )  (fp32 H) ----
        mma_gemm<64,128,128,128,64,EPI_RELU_ADD,false>(SU+OFF_SP1,144, SU+OFF_SP2,144, pkl+PK_WU, bu+l*128, Sf+OFF_H, LDH, 0);
        __syncthreads();

        // ---- FFN in 2 chunks of 4 nodes; mid split 32x528 overlays K+V ----
        #pragma unroll 1
        for (int c = 0; c < 2; c++) {
            #pragma unroll
            for (int it = 0; it < 2; it++) {
                int p = it * 16 + wid;            // 0..31 = (r*4 + nn)
                int r = p >> 2, nn = p & 3;
                ln_split(Sf + OFF_H + (r*8 + c*4 + nn)*LDH, SU + OFF_Q + p*144, g2, b2);
            }
            __syncthreads();
            mma_gemm<32,128,512,0,32,EPI_GELU,true>(SU+OFF_Q,144, nullptr,0, pkl+PK_WF1, bf1+l*512, SU+OFF_K, 528, 0);
            __syncthreads();
            mma_gemm<32,512,128,0,4,EPI_ADD,false>(SU+OFF_K,528, nullptr,0, pkl+PK_WF2, bf2+l*128,
                                                   Sf+OFF_H + c*4*LDH, LDH, 8*LDH);
            __syncthreads();
        }
    }

    // ---- convert H -> splitH (SP1: batch stride 1168, node stride 144) ----
    for (int idx = t; idx < 4096; idx += NT) {          // 64 rows x 64 pairs
        int nr = idx >> 6, pr = idx & 63;
        float2 hv = *(const float2*)(Sf + OFF_H + nr*LDH + 2*pr);
        store_split_pair(SU + OFF_SP1 + (nr >> 3) * 1168 + (nr & 7) * 144, pr >> 3, pr & 7, hv.x, hv.y);
    }
    __syncthreads();
    // agg = gelu(flat @ Wa + ba) -> split (SP2, 144)
    mma_gemm<8,1024,128,0,8,EPI_GELU,true, 8,144>(SU+OFF_SP1,1168, nullptr,0, g_packed+PK_WA, ba, SU+OFF_SP2, 144, 0);
    __syncthreads();
    // out = agg @ Wout + bout (global fp32)
    mma_gemm<8,128,128,0,8,EPI_STORE,false>(SU+OFF_SP2,144, nullptr,0, g_packed+PK_WOUT, bout,
                                            out + (size_t)row0*128, 128, 0);
}

extern "C" void kernel_launch(void* const* d_in, const int* in_sizes, int n_in,
                              void* d_out, int out_size)
{
    (void)n_in; (void)out_size;
    const float* x     = (const float*)d_in[0];
    const float* Wp    = (const float*)d_in[1];
    const float* bp    = (const float*)d_in[2];
    const float* ln1_g = (const float*)d_in[3];
    const float* ln1_b = (const float*)d_in[4];
    const float* Wq    = (const float*)d_in[5];
    const float* bq    = (const float*)d_in[6];
    const float* Wk    = (const float*)d_in[7];
    const float* bk    = (const float*)d_in[8];
    const float* Wv    = (const float*)d_in[9];
    const float* bv    = (const float*)d_in[10];
    const float* Wo    = (const float*)d_in[11];
    const float* bo    = (const float*)d_in[12];
    const float* Wu    = (const float*)d_in[13];
    const float* bu    = (const float*)d_in[14];
    const float* ln2_g = (const float*)d_in[15];
    const float* ln2_b = (const float*)d_in[16];
    const float* Wf1   = (const float*)d_in[17];
    const float* bf1   = (const float*)d_in[18];
    const float* Wf2   = (const float*)d_in[19];
    const float* bf2   = (const float*)d_in[20];
    const float* Wa    = (const float*)d_in[21];
    const float* ba    = (const float*)d_in[22];
    const float* Wout  = (const float*)d_in[23];
    const float* bout  = (const float*)d_in[24];

    const int Bsz = in_sizes[0] / 256;       // DIN = 256
    const int grid = Bsz / ROWS;
    const size_t smem = SMEM_U32 * sizeof(unsigned);

    pack_weights<<<1080, 256>>>(Wp, Wq, Wk, Wv, Wo, Wu, Wf1, Wf2, Wa, Wout, bq, bk, bv);

    cudaFuncSetAttribute(fused_reasoner, cudaFuncAttributeMaxDynamicSharedMemorySize, (int)smem);
    fused_reasoner<<<grid, NT, smem>>>(
        x, bp, ln1_g, ln1_b, bo, bu, ln2_g, ln2_b,
        bf1, bf2, ba, bout, (float*)d_out);
}

// round 17
// speedup vs baseline: 1.0579x; 1.0014x over previous
#include <cuda_runtime.h>
#include <math.h>

#define NT 512
#define ROWS 8
#define LDH 132            // fp32 H row stride (132%32==4)

// ---- per-half smem regions (u32 units, relative to half base) ----
#define HH    0            // H fp32: 32 x 132 = 4224
#define HSP1  4224         // hn split 32x144 = 4608
#define HFK   8832         // K fp32 32x132; FFN mid split 16x528 spans HFK+HFV
#define HFV   13056        // V fp32 32x132
#define HQA   17280        // Q fp32 32x132 / att split 32x144 / hn2 split 16x144
#define HSP2  21888        // attO split 32x144; (half0: x split 8x272 pre-loop, agg post-loop)
#define HALF  26496        // per-half stride
#define SMEM_U32 52992     // 211,968 bytes
// post-loop: splitH (8x1168=9344) at SU+HFK (spans half0 FK/FV/QA start)

// ---- packed (pre-split bf16) weight scratch: uint4{bh0,bh1,bl0,bl1} per [k16][jt][lane] ----
#define PK_WP     0
#define PK_L0     65536
#define PK_LSTR   57344
#define PK_WQ     0
#define PK_WK     4096
#define PK_WV     8192
#define PK_WO     12288
#define PK_WU     16384
#define PK_WF1    24576
#define PK_WF2    40960
#define PK_WA     237568
#define PK_WOUT   270336
#define PK_TOTAL  274432

__device__ uint4 g_packed[PK_TOTAL];

enum { EPI_STORE=0, EPI_GELU=2, EPI_ADD=3, EPI_RELU_ADD=4 };

__device__ __forceinline__ float gelu_f(float v) {
    return 0.5f * v * (1.0f + erff(v * 0.70710678118654752440f));
}
__device__ __forceinline__ void hbar(int id) {
    asm volatile("bar.sync %0, %1;" :: "r"(id), "r"(256) : "memory");
}

// ---- bf16 mma helpers ----
__device__ __forceinline__ void mma_bf16(float* d, const unsigned* a, const unsigned* b) {
    asm("mma.sync.aligned.m16n8k16.row.col.f32.bf16.bf16.f32 "
        "{%0,%1,%2,%3}, {%4,%5,%6,%7}, {%8,%9}, {%0,%1,%2,%3};"
        : "+f"(d[0]), "+f"(d[1]), "+f"(d[2]), "+f"(d[3])
        : "r"(a[0]), "r"(a[1]), "r"(a[2]), "r"(a[3]), "r"(b[0]), "r"(b[1]));
}
__device__ __forceinline__ unsigned cvt_bf16x2(float hi_elem, float lo_elem) {
    unsigned r;
    asm("cvt.rn.bf16x2.f32 %0, %1, %2;" : "=r"(r) : "f"(hi_elem), "f"(lo_elem));
    return r;
}
__device__ __forceinline__ float bf_lo(unsigned r) { return __uint_as_float(r << 16); }
__device__ __forceinline__ float bf_hi(unsigned r) { return __uint_as_float(r & 0xFFFF0000u); }
__device__ __forceinline__ void split_bf16(float x, float y, unsigned& hi, unsigned& lo) {
    hi = cvt_bf16x2(y, x);
    lo = cvt_bf16x2(y - bf_hi(hi), x - bf_lo(hi));
}
__device__ __forceinline__ int pslot(int p) { return (p < 4) ? p * 4 : (p - 4) * 4 + 2; }
__device__ __forceinline__ void store_split_pair(unsigned* row, int w, int p, float x, float y) {
    unsigned hi, lo; split_bf16(x, y, hi, lo);
    *(uint2*)(row + w * 16 + pslot(p)) = make_uint2(hi, lo);
}

// ---- weight pre-splitter (fragment-order packed bf16; R10 format) ----
__global__ void pack_weights(const float* __restrict__ Wp, const float* __restrict__ Wq,
        const float* __restrict__ Wk, const float* __restrict__ Wv, const float* __restrict__ Wo,
        const float* __restrict__ Wu, const float* __restrict__ Wf1, const float* __restrict__ Wf2,
        const float* __restrict__ Wa, const float* __restrict__ Wout)
{
    const float* src[24]; int Js[24]; long base[24]; int ents[24];
    int n = 0; long off = 0;
    #define ADDSEG(w, K_, J_) { src[n]=(w); Js[n]=(J_); ents[n]=(K_)*(J_)/4; base[n]=off; off+=(K_)*(J_)/4; n++; }
    ADDSEG(Wp, 256, 1024);
    for (int l = 0; l < 3; l++) {
        ADDSEG(Wq+l*16384,128,128); ADDSEG(Wk+l*16384,128,128); ADDSEG(Wv+l*16384,128,128);
        ADDSEG(Wo+l*16384,128,128); ADDSEG(Wu+l*32768,256,128);
        ADDSEG(Wf1+l*65536,128,512); ADDSEG(Wf2+l*65536,512,128);
    }
    ADDSEG(Wa,1024,128); ADDSEG(Wout,128,128);
    #undef ADDSEG

    for (long idx = blockIdx.x*(long)blockDim.x + threadIdx.x; idx < PK_TOTAL;
         idx += (long)gridDim.x * blockDim.x) {
        int s = 0;
        while (s < 23 && idx >= base[s] + ents[s]) s++;
        long e = idx - base[s];
        const float* W = src[s]; const int J = Js[s];
        int lane = (int)(e & 31);
        long tmp = e >> 5;
        int jt  = (int)(tmp % (J/8));
        int k16 = (int)(tmp / (J/8));
        int tid = lane & 3, group = lane >> 2;
        int j  = jt*8 + group;
        int k0 = k16*16 + 2*tid;
        float w0 = W[(size_t)(k0  )*J + j];
        float w1 = W[(size_t)(k0+1)*J + j];
        float w2 = W[(size_t)(k0+8)*J + j];
        float w3 = W[(size_t)(k0+9)*J + j];
        unsigned bh0, bl0, bh1, bl1;
        split_bf16(w0, w1, bh0, bl0);
        split_bf16(w2, w3, bh1, bl1);
        g_packed[idx] = make_uint4(bh0, bh1, bl0, bl1);
    }
}

// Tensor-core GEMM: A pre-split in smem, B pre-split packed in global.
// NWARP=16: full-block; NWARP=8: half-block (both halves call with their own pointers).
template<int M,int K,int J,int K2,int MI,int EPI,bool OSPLIT,
         int KI16=1<<28,int LDKW=0,int JI=1<<28,int SJ=0,int NWARP=16>
__device__ __forceinline__ void mma_gemm(
    const unsigned* __restrict__ A,  int lda,
    const unsigned* __restrict__ A2, int lda2,
    const uint4* __restrict__ Wpk,
    const float* __restrict__ bias,
    void* __restrict__ outp, int s_in, int s_out)
{
    constexpr int TM16   = (M + 15) / 16;
    constexpr int TJ8    = J / 8;
    static_assert((TM16 * TJ8) % NWARP == 0, "tile count must divide warps");
    constexpr int NT_S   = TM16 * TJ8 / NWARP;
    constexpr int TJSTEP = NWARP / TM16;
    constexpr bool PRED  = (M % 16) != 0;

    const int w     = (threadIdx.x >> 5) & (NWARP - 1);
    const int lane  = threadIdx.x & 31;
    const int group = lane >> 2;
    const int tid   = lane & 3;
    const int tm    = w % TM16;
    const int tj0   = w / TM16;
    const int r0    = tm * 16 + group;
    const int r1    = r0 + 8;

    const uint4* wp = Wpk + tj0 * 32 + lane;
    const unsigned* Ar0 = A + r0 * lda + tid * 4;
    const unsigned* Ar1 = A + r1 * lda + tid * 4;

    float acc[NT_S][4];
    #pragma unroll
    for (int s = 0; s < NT_S; s++) { acc[s][0]=0.f; acc[s][1]=0.f; acc[s][2]=0.f; acc[s][3]=0.f; }

    #pragma unroll 2
    for (int ii = 0; ii < K/16; ii++) {
        const int woff = (ii / KI16) * LDKW + (ii % KI16) * 16;
        uint4 a0, a1;
        if (!PRED || r0 < M) a0 = *(const uint4*)(Ar0 + woff); else a0 = make_uint4(0,0,0,0);
        if (!PRED || r1 < M) a1 = *(const uint4*)(Ar1 + woff); else a1 = make_uint4(0,0,0,0);
        unsigned ah[4] = {a0.x, a1.x, a0.z, a1.z};
        unsigned al[4] = {a0.y, a1.y, a0.w, a1.w};
        #pragma unroll
        for (int s = 0; s < NT_S; s++) {
            uint4 b = wp[s * TJSTEP * 32];
            unsigned bh[2] = {b.x, b.y}, bl[2] = {b.z, b.w};
            mma_bf16(acc[s], ah, bh);
            mma_bf16(acc[s], ah, bl);
            mma_bf16(acc[s], al, bh);
        }
        wp += TJ8 * 32;
    }
    if constexpr (K2 > 0) {
        const unsigned* B0 = A2 + r0 * lda2 + tid * 4;
        const unsigned* B1 = A2 + r1 * lda2 + tid * 4;
        #pragma unroll 2
        for (int ii = 0; ii < K2/16; ii++) {
            uint4 a0 = *(const uint4*)(B0 + ii * 16);
            uint4 a1 = *(const uint4*)(B1 + ii * 16);
            unsigned ah[4] = {a0.x, a1.x, a0.z, a1.z};
            unsigned al[4] = {a0.y, a1.y, a0.w, a1.w};
            #pragma unroll
            for (int s = 0; s < NT_S; s++) {
                uint4 b = wp[s * TJSTEP * 32];
                unsigned bh[2] = {b.x, b.y}, bl[2] = {b.z, b.w};
                mma_bf16(acc[s], ah, bh);
                mma_bf16(acc[s], ah, bl);
                mma_bf16(acc[s], al, bh);
            }
            wp += TJ8 * 32;
        }
    }

    // epilogue
    #pragma unroll
    for (int s = 0; s < NT_S; s++) {
        const int j0 = (tj0 + s * TJSTEP) * 8;
        const int c0 = j0 + 2 * tid;
        const float b0 = bias[c0], b1 = bias[c0 + 1];
        float v00 = acc[s][0] + b0, v01 = acc[s][1] + b1;
        float v10 = acc[s][2] + b0, v11 = acc[s][3] + b1;
        if constexpr (EPI == EPI_GELU) { v00=gelu_f(v00); v01=gelu_f(v01); v10=gelu_f(v10); v11=gelu_f(v11); }
        if constexpr (OSPLIT) {
            unsigned* ob = (unsigned*)outp;
            const int off = (c0 >> 4) * 16 + tid * 4 + ((j0 >> 3) & 1) * 2;
            if (!PRED || r0 < M) {
                unsigned hi, lo; split_bf16(v00, v01, hi, lo);
                *(uint2*)(ob + r0 * s_in + off) = make_uint2(hi, lo);
            }
            if (!PRED || r1 < M) {
                unsigned hi, lo; split_bf16(v10, v11, hi, lo);
                *(uint2*)(ob + r1 * s_in + off) = make_uint2(hi, lo);
            }
        } else {
            float* of = (float*)outp;
            const int jo = (c0 / JI) * SJ + (c0 % JI);
            if (!PRED || r0 < M) {
                float* p = of + (r0 % MI) * s_in + (r0 / MI) * s_out + jo;
                if constexpr (EPI == EPI_ADD)      { p[0] += v00; p[1] += v01; }
                else if constexpr (EPI == EPI_RELU_ADD) { p[0] += fmaxf(v00,0.f); p[1] += fmaxf(v01,0.f); }
                else { p[0] = v00; p[1] = v01; }
            }
            if (!PRED || r1 < M) {
                float* p = of + (r1 % MI) * s_in + (r1 / MI) * s_out + jo;
                if constexpr (EPI == EPI_ADD)      { p[0] += v10; p[1] += v11; }
                else if constexpr (EPI == EPI_RELU_ADD) { p[0] += fmaxf(v10,0.f); p[1] += fmaxf(v11,0.f); }
                else { p[0] = v10; p[1] = v11; }
            }
        }
    }
}

// LayerNorm over 128 elems; lane owns 4 consecutive elems; writes split format.
__device__ __forceinline__ void ln_split(const float* __restrict__ src, unsigned* __restrict__ dst,
                                         const float* __restrict__ g, const float* __restrict__ b)
{
    const int lane = threadIdx.x & 31;
    float4 v = *(const float4*)(src + lane * 4);
    float s  = v.x + v.y + v.z + v.w;
    float sq = v.x*v.x + v.y*v.y + v.z*v.z + v.w*v.w;
    #pragma unroll
    for (int o = 16; o > 0; o >>= 1) {
        s  += __shfl_xor_sync(0xffffffffu, s,  o);
        sq += __shfl_xor_sync(0xffffffffu, sq, o);
    }
    float mean = s * (1.f/128.f);
    float rstd = rsqrtf(sq * (1.f/128.f) - mean*mean + 1e-5f);
    float4 gg = *(const float4*)(g + lane * 4);
    float4 bb = *(const float4*)(b + lane * 4);
    float y0 = (v.x-mean)*rstd*gg.x + bb.x;
    float y1 = (v.y-mean)*rstd*gg.y + bb.y;
    float y2 = (v.z-mean)*rstd*gg.z + bb.z;
    float y3 = (v.w-mean)*rstd*gg.w + bb.w;
    const int w  = lane >> 2;
    const int p0 = (lane & 3) * 2;
    store_split_pair(dst, w, p0,     y0, y1);
    store_split_pair(dst, w, p0 + 1, y2, y3);
}

__global__ void __launch_bounds__(NT, 1) fused_reasoner(
    const float* __restrict__ x,
    const float* __restrict__ bp,
    const float* __restrict__ ln1_g, const float* __restrict__ ln1_b,
    const float* __restrict__ bq, const float* __restrict__ bk,
    const float* __restrict__ bv, const float* __restrict__ bo,
    const float* __restrict__ bu,
    const float* __restrict__ ln2_g, const float* __restrict__ ln2_b,
    const float* __restrict__ bf1, const float* __restrict__ bf2,
    const float* __restrict__ ba, const float* __restrict__ bout,
    float* __restrict__ out)
{
    extern __shared__ unsigned SU[];
    float* Sf = (float*)SU;
    const int t = threadIdx.x;
    const int wid = t >> 5;              // 0..15
    const int half = wid >> 3;           // 0 or 1
    const int lw = wid & 7;              // warp index within half
    const int tl = t & 255;              // thread index within half
    const int bid = 1 + half;            // named barrier id for this half
    const int row0 = blockIdx.x * ROWS;

    unsigned* SUh = SU + half * HALF;    // this half's region base
    float*    Sfh = (float*)SUh;

    // ---- stage x tile (8 rows x 256) into split format at half0 SP2 (stride 272) ----
    for (int idx = t; idx < 1024; idx += NT) {          // 8*128 pairs
        int nr = idx >> 7, pr = idx & 127;
        float2 xv = *(const float2*)(x + (size_t)(row0 + nr) * 256 + 2 * pr);
        store_split_pair(SU + HSP2 + nr * 272, pr >> 3, pr & 7, xv.x, xv.y);
    }
    __syncthreads();
    // h = x @ Wp + bp: batch row m -> (m%4)*8*LDH + (m/4)*HALF; col j -> node (j/128)*LDH
    mma_gemm<8,256,1024,0,4,EPI_STORE,false, (1<<28),0, 128,LDH, 16>(
        SU+HSP2,272, nullptr,0, g_packed+PK_WP, bp, Sf+HH, 8*LDH, HALF);
    __syncthreads();

    // ================= layer loop: two independent half-pipelines =================
    #pragma unroll 1
    for (int l = 0; l < 3; l++) {
        const uint4* pkl = g_packed + PK_L0 + (long)l * PK_LSTR;
        const float* g1 = ln1_g + l*128;   const float* b1 = ln1_b + l*128;
        const float* g2 = ln2_g + l*128;   const float* b2 = ln2_b + l*128;

        // ---- LN1 -> hn split (HSP1, stride 144): 32 rows, 8 warps x 4 ----
        #pragma unroll
        for (int it = 0; it < 4; it++) {
            int p = it * 8 + lw;
            ln_split(Sfh + HH + p*LDH, SUh + HSP1 + p*144, g1, b1);
        }
        hbar(bid);

        // ---- Q,K,V projections (fp32 outs) ----
        mma_gemm<32,128,128,0,32,EPI_STORE,false,(1<<28),0,(1<<28),0,8>(
            SUh+HSP1,144, nullptr,0, pkl+PK_WQ, bq+l*128, Sfh+HQA, LDH, 0);
        mma_gemm<32,128,128,0,32,EPI_STORE,false,(1<<28),0,(1<<28),0,8>(
            SUh+HSP1,144, nullptr,0, pkl+PK_WK, bk+l*128, Sfh+HFK, LDH, 0);
        mma_gemm<32,128,128,0,32,EPI_STORE,false,(1<<28),0,(1<<28),0,8>(
            SUh+HSP1,144, nullptr,0, pkl+PK_WV, bv+l*128, Sfh+HFV, LDH, 0);
        hbar(bid);

        // ---- causal attention: 128 of 256 half-threads = (row, head, query-node) ----
        float pr8[8]; float inv = 0.f;
        int ar, ahd, an;
        if (tl < 128) {
            ar = tl >> 5; ahd = (tl >> 3) & 3; an = tl & 7;
            const float* qp = Sfh + HQA + (ar*8 + an)*LDH + ahd*32;
            float mx = -1e30f;
            #pragma unroll
            for (int m = 0; m < 8; m++) {
                if (m <= an) {
                    const float* kp = Sfh + HFK + (ar*8 + m)*LDH + ahd*32;
                    float sc = 0.f;
                    #pragma unroll
                    for (int d = 0; d < 32; d++) sc += qp[d] * kp[d];
                    sc *= 0.17677669529663688f;
                    pr8[m] = sc;
                    mx = fmaxf(mx, sc);
                }
            }
            float sum = 0.f;
            #pragma unroll
            for (int m = 0; m < 8; m++) if (m <= an) { pr8[m] = __expf(pr8[m] - mx); sum += pr8[m]; }
            inv = 1.f / sum;
        }
        hbar(bid);   // all Q reads done before split overwrite
        if (tl < 128) {
            float o[32];
            #pragma unroll
            for (int d = 0; d < 32; d++) {
                float acc = 0.f;
                #pragma unroll
                for (int m = 0; m < 8; m++)
                    if (m <= an) acc += pr8[m] * (Sfh + HFV)[(ar*8 + m)*LDH + ahd*32 + d];
                o[d] = acc * inv;
            }
            unsigned* ad = SUh + HQA + (ar*8 + an)*144 + ahd*32;
            #pragma unroll
            for (int i = 0; i < 16; i++)
                store_split_pair(ad, i >> 3, i & 7, o[2*i], o[2*i+1]);
        }
        hbar(bid);

        // ---- attO = att @ Wo + bo -> split (HSP2, 144) ----
        mma_gemm<32,128,128,0,32,EPI_STORE,true,(1<<28),0,(1<<28),0,8>(
            SUh+HQA,144, nullptr,0, pkl+PK_WO, bo+l*128, SUh+HSP2, 144, 0);
        hbar(bid);

        // ---- h += relu( [hn | attO] @ Wu + bu )  (fp32 H) ----
        mma_gemm<32,128,128,128,32,EPI_RELU_ADD,false,(1<<28),0,(1<<28),0,8>(
            SUh+HSP1,144, SUh+HSP2,144, pkl+PK_WU, bu+l*128, Sfh+HH, LDH, 0);
        hbar(bid);

        // ---- FFN in 2 chunks of 4 nodes (16 rows); mid split 16x528 overlays HFK+HFV ----
        #pragma unroll 1
        for (int c = 0; c < 2; c++) {
            #pragma unroll
            for (int it = 0; it < 2; it++) {
                int p = it * 8 + lw;              // 0..15 = (r*4 + nn)
                int r = p >> 2, nn = p & 3;
                ln_split(Sfh + HH + (r*8 + c*4 + nn)*LDH, SUh + HQA + p*144, g2, b2);
            }
            hbar(bid);
            mma_gemm<16,128,512,0,16,EPI_GELU,true,(1<<28),0,(1<<28),0,8>(
                SUh+HQA,144, nullptr,0, pkl+PK_WF1, bf1+l*512, SUh+HFK, 528, 0);
            hbar(bid);
            mma_gemm<16,512,128,0,4,EPI_ADD,false,(1<<28),0,(1<<28),0,8>(
                SUh+HFK,528, nullptr,0, pkl+PK_WF2, bf2+l*128, Sfh+HH + c*4*LDH, LDH, 8*LDH);
            hbar(bid);
        }
    }
    __syncthreads();   // both halves done

    // ---- convert H -> splitH at SU+HFK (batch stride 1168, node stride 144) ----
    for (int idx = t; idx < 4096; idx += NT) {          // 64 rows x 64 pairs
        int nr = idx >> 6, pr = idx & 63;
        int r = nr >> 3, nn = nr & 7;
        const float* hs = Sf + (r >> 2) * HALF + HH + ((r & 3)*8 + nn)*LDH;
        store_split_pair(SU + HFK + r * 1168 + nn * 144, pr >> 3, pr & 7,
                         hs[2*pr], hs[2*pr + 1]);
    }
    __syncthreads();
    // agg = gelu(flat @ Wa + ba) -> split (half0 SP2, 144)
    mma_gemm<8,1024,128,0,8,EPI_GELU,true, 8,144,(1<<28),0,16>(
        SU+HFK,1168, nullptr,0, g_packed+PK_WA, ba, SU+HSP2, 144, 0);
    __syncthreads();
    // out = agg @ Wout + bout (global fp32)
    mma_gemm<8,128,128,0,8,EPI_STORE,false>(SU+HSP2,144, nullptr,0, g_packed+PK_WOUT, bout,
                                            out + (size_t)row0*128, 128, 0);
}

extern "C" void kernel_launch(void* const* d_in, const int* in_sizes, int n_in,
                              void* d_out, int out_size)
{
    (void)n_in; (void)out_size;
    const float* x     = (const float*)d_in[0];
    const float* Wp    = (const float*)d_in[1];
    const float* bp    = (const float*)d_in[2];
    const float* ln1_g = (const float*)d_in[3];
    const float* ln1_b = (const float*)d_in[4];
    const float* Wq    = (const float*)d_in[5];
    const float* bq    = (const float*)d_in[6];
    const float* Wk    = (const float*)d_in[7];
    const float* bk    = (const float*)d_in[8];
    const float* Wv    = (const float*)d_in[9];
    const float* bv    = (const float*)d_in[10];
    const float* Wo    = (const float*)d_in[11];
    const float* bo    = (const float*)d_in[12];
    const float* Wu    = (const float*)d_in[13];
    const float* bu    = (const float*)d_in[14];
    const float* ln2_g = (const float*)d_in[15];
    const float* ln2_b = (const float*)d_in[16];
    const float* Wf1   = (const float*)d_in[17];
    const float* bf1   = (const float*)d_in[18];
    const float* Wf2   = (const float*)d_in[19];
    const float* bf2   = (const float*)d_in[20];
    const float* Wa    = (const float*)d_in[21];
    const float* ba    = (const float*)d_in[22];
    const float* Wout  = (const float*)d_in[23];
    const float* bout  = (const float*)d_in[24];

    const int Bsz = in_sizes[0] / 256;       // DIN = 256
    const int grid = Bsz / ROWS;
    const size_t smem = SMEM_U32 * sizeof(unsigned);

    pack_weights<<<1072, 256>>>(Wp, Wq, Wk, Wv, Wo, Wu, Wf1, Wf2, Wa, Wout);

    cudaFuncSetAttribute(fused_reasoner, cudaFuncAttributeMaxDynamicSharedMemorySize, (int)smem);
    fused_reasoner<<<grid, NT, smem>>>(
        x, bp, ln1_g, ln1_b, bq, bk, bv, bo, bu, ln2_g, ln2_b,
        bf1, bf2, ba, bout, (float*)d_out);
}